// round 1
// baseline (speedup 1.0000x reference)
#include <cuda_runtime.h>
#include <math.h>
#include <stdint.h>

// Problem constants
#define Bsz  4
#define Lseq 4096
#define DIMc 1024
#define Hn   16
#define DHc  64
#define NFc  64
#define Mrows (Bsz * Lseq)          // 16384
#define BHc   (Bsz * Hn)            // 64
#define EPSf  1e-6f

// ---------------------------------------------------------------------------
// Scratch (device globals; allocation inside kernel_launch is forbidden)
// ---------------------------------------------------------------------------
__device__ float g_q[(size_t)Mrows * DIMc];
__device__ float g_k[(size_t)Mrows * DIMc];
__device__ float g_v[(size_t)Mrows * DIMc];
__device__ float g_ctx[(size_t)Mrows * DIMc];
__device__ float g_logits[(size_t)BHc * Lseq * NFc];
__device__ float g_phi[(size_t)BHc * Lseq * NFc];
__device__ float g_N[BHc * NFc * DHc];
__device__ float g_D[BHc * NFc];
__device__ float g_M[BHc];

// ---------------------------------------------------------------------------
// Helpers
// ---------------------------------------------------------------------------
__device__ __forceinline__ void atomicMaxFloat(float* addr, float val) {
    int* ai = (int*)addr;
    int old = *ai;
    while (__int_as_float(old) < val) {
        int assumed = old;
        old = atomicCAS(ai, assumed, __float_as_int(val));
        if (old == assumed) break;
    }
}

// ---------------------------------------------------------------------------
// Init: zero N/D, set M = -inf
// ---------------------------------------------------------------------------
__global__ void init_kernel() {
    int i = blockIdx.x * blockDim.x + threadIdx.x;
    if (i < BHc * NFc * DHc) g_N[i] = 0.0f;
    if (i < BHc * NFc)       g_D[i] = 0.0f;
    if (i < BHc)             g_M[i] = -1e30f;
}

// ---------------------------------------------------------------------------
// SGEMM (NT): C[M,N] = A[M,K] * W[N,K]^T + bias[N];  N = K = DIMc fixed.
// BM = BN = 128, BK = 16, 256 threads, 8x8 register micro-tile per thread.
// ---------------------------------------------------------------------------
__global__ void __launch_bounds__(256) sgemm_nt(const float* __restrict__ A,
                                                const float* __restrict__ W,
                                                const float* __restrict__ bias,
                                                float* __restrict__ C) {
    __shared__ float As[16][132];
    __shared__ float Bs[16][132];
    int t  = threadIdx.x;
    int bm = blockIdx.y * 128;
    int bn = blockIdx.x * 128;
    int tx = t & 15, ty = t >> 4;
    int lrow = t >> 2;            // 0..63
    int lcol = (t & 3) << 2;      // 0,4,8,12

    float acc[8][8];
    #pragma unroll
    for (int i = 0; i < 8; i++)
        #pragma unroll
        for (int j = 0; j < 8; j++) acc[i][j] = 0.0f;

    for (int k0 = 0; k0 < DIMc; k0 += 16) {
        #pragma unroll
        for (int r = 0; r < 2; r++) {
            int row = lrow + r * 64;
            float4 a = *(const float4*)(A + (size_t)(bm + row) * DIMc + k0 + lcol);
            As[lcol + 0][row] = a.x; As[lcol + 1][row] = a.y;
            As[lcol + 2][row] = a.z; As[lcol + 3][row] = a.w;
            float4 w = *(const float4*)(W + (size_t)(bn + row) * DIMc + k0 + lcol);
            Bs[lcol + 0][row] = w.x; Bs[lcol + 1][row] = w.y;
            Bs[lcol + 2][row] = w.z; Bs[lcol + 3][row] = w.w;
        }
        __syncthreads();
        #pragma unroll
        for (int k = 0; k < 16; k++) {
            float a[8], bb[8];
            #pragma unroll
            for (int i = 0; i < 8; i++) a[i] = As[k][ty * 8 + i];
            #pragma unroll
            for (int j = 0; j < 8; j++) bb[j] = Bs[k][tx * 8 + j];
            #pragma unroll
            for (int i = 0; i < 8; i++)
                #pragma unroll
                for (int j = 0; j < 8; j++)
                    acc[i][j] = fmaf(a[i], bb[j], acc[i][j]);
        }
        __syncthreads();
    }

    #pragma unroll
    for (int i = 0; i < 8; i++) {
        size_t row = (size_t)(bm + ty * 8 + i);
        int col = bn + tx * 8;
        #pragma unroll
        for (int j4 = 0; j4 < 2; j4++) {
            float4 o;
            o.x = acc[i][j4 * 4 + 0] + bias[col + j4 * 4 + 0];
            o.y = acc[i][j4 * 4 + 1] + bias[col + j4 * 4 + 1];
            o.z = acc[i][j4 * 4 + 2] + bias[col + j4 * 4 + 2];
            o.w = acc[i][j4 * 4 + 3] + bias[col + j4 * 4 + 3];
            *(float4*)(C + row * DIMc + col + j4 * 4) = o;
        }
    }
}

// ---------------------------------------------------------------------------
// Logits + phi kernel.
// grid: (Lseq/32, B*H), 256 threads (8 warps x 4 rows).
// logits[bh,l,f] = k . W0[:,f] - 0.5*||k||^2 ; atomicMax of block max into g_M
// phi[bh,l,f]    = softmax_f(q . W0[:,f])
// ---------------------------------------------------------------------------
__global__ void __launch_bounds__(256) logits_kernel(const float* __restrict__ Wrf) {
    int bh = blockIdx.y;
    int b = bh >> 4, h = bh & 15;
    int l0 = blockIdx.x * 32;

    __shared__ float W0s[DHc][NFc];
    __shared__ float ks[32][DHc];
    __shared__ float qs[32][DHc];
    __shared__ float wmax[8];

    int t = threadIdx.x;
    for (int e = t; e < DHc * NFc; e += 256)
        W0s[e / NFc][e % NFc] = Wrf[h * DHc * NFc + e];
    for (int e = t; e < 32 * DHc; e += 256) {
        int row = e >> 6, d = e & 63;
        size_t g = (size_t)(b * Lseq + l0 + row) * DIMc + h * DHc + d;
        ks[row][d] = g_k[g];
        qs[row][d] = g_q[g];
    }
    __syncthreads();

    int warp = t >> 5, lane = t & 31;
    float lmax = -1e30f;

    #pragma unroll 1
    for (int r = 0; r < 4; r++) {
        int l = warp * 4 + r;
        float aK0 = 0.f, aK1 = 0.f, aQ0 = 0.f, aQ1 = 0.f, kk = 0.f;
        #pragma unroll
        for (int d = 0; d < DHc; d++) {
            float kv = ks[l][d], qv = qs[l][d];
            float w0 = W0s[d][lane], w1 = W0s[d][lane + 32];
            aK0 = fmaf(kv, w0, aK0); aK1 = fmaf(kv, w1, aK1);
            aQ0 = fmaf(qv, w0, aQ0); aQ1 = fmaf(qv, w1, aQ1);
            kk  = fmaf(kv, kv, kk);
        }
        float lg0 = aK0 - 0.5f * kk;
        float lg1 = aK1 - 0.5f * kk;
        lmax = fmaxf(lmax, fmaxf(lg0, lg1));
        size_t base = ((size_t)bh * Lseq + l0 + l) * NFc;
        g_logits[base + lane]      = lg0;
        g_logits[base + lane + 32] = lg1;

        // per-position softmax over 64 features (warp-collective)
        float pm = fmaxf(aQ0, aQ1);
        #pragma unroll
        for (int o = 16; o > 0; o >>= 1)
            pm = fmaxf(pm, __shfl_xor_sync(0xffffffffu, pm, o));
        float e0 = __expf(aQ0 - pm), e1 = __expf(aQ1 - pm);
        float s = e0 + e1;
        #pragma unroll
        for (int o = 16; o > 0; o >>= 1)
            s += __shfl_xor_sync(0xffffffffu, s, o);
        float inv = 1.0f / s;
        g_phi[base + lane]      = e0 * inv;
        g_phi[base + lane + 32] = e1 * inv;
    }

    #pragma unroll
    for (int o = 16; o > 0; o >>= 1)
        lmax = fmaxf(lmax, __shfl_xor_sync(0xffffffffu, lmax, o));
    if (lane == 0) wmax[warp] = lmax;
    __syncthreads();
    if (t == 0) {
        float m = wmax[0];
        #pragma unroll
        for (int i = 1; i < 8; i++) m = fmaxf(m, wmax[i]);
        atomicMaxFloat(&g_M[bh], m);
    }
}

// ---------------------------------------------------------------------------
// N/D accumulation: per (b,h) chunk of 256 L rows,
//   Npart[f,d] = sum_l exp(logit[l,f]-m) * v[l,d], Dpart[f] = sum_l exp(...)
// grid: (Lseq/256, B*H), 256 threads, 4x4 micro-tile per thread over (f,d).
// ---------------------------------------------------------------------------
__global__ void __launch_bounds__(256) nd_kernel() {
    int bh = blockIdx.y;
    int b = bh >> 4, h = bh & 15;
    int l0 = blockIdx.x * 256;

    __shared__ float Es[16][NFc];
    __shared__ float Vs[16][DHc];

    int t = threadIdx.x;
    float m = g_M[bh];
    int tf = (t >> 4) << 2;   // 0..60  (feature group)
    int td = (t & 15) << 2;   // 0..60  (dh group)
    int lrow = t >> 4;        // 0..15 (loader row)
    int lc4  = (t & 15) << 2; // 0..60 (loader col group)

    float acc[4][4];
    #pragma unroll
    for (int i = 0; i < 4; i++)
        #pragma unroll
        for (int j = 0; j < 4; j++) acc[i][j] = 0.0f;
    float dacc[4] = {0.f, 0.f, 0.f, 0.f};

    for (int lt = 0; lt < 256; lt += 16) {
        int l = l0 + lt + lrow;
        float4 lg = *(const float4*)&g_logits[((size_t)bh * Lseq + l) * NFc + lc4];
        Es[lrow][lc4 + 0] = __expf(lg.x - m);
        Es[lrow][lc4 + 1] = __expf(lg.y - m);
        Es[lrow][lc4 + 2] = __expf(lg.z - m);
        Es[lrow][lc4 + 3] = __expf(lg.w - m);
        float4 vv = *(const float4*)&g_v[(size_t)(b * Lseq + l) * DIMc + h * DHc + lc4];
        Vs[lrow][lc4 + 0] = vv.x; Vs[lrow][lc4 + 1] = vv.y;
        Vs[lrow][lc4 + 2] = vv.z; Vs[lrow][lc4 + 3] = vv.w;
        __syncthreads();
        #pragma unroll
        for (int kk = 0; kk < 16; kk++) {
            float a[4], bb[4];
            #pragma unroll
            for (int i = 0; i < 4; i++) a[i]  = Es[kk][tf + i];
            #pragma unroll
            for (int j = 0; j < 4; j++) bb[j] = Vs[kk][td + j];
            #pragma unroll
            for (int i = 0; i < 4; i++)
                #pragma unroll
                for (int j = 0; j < 4; j++)
                    acc[i][j] = fmaf(a[i], bb[j], acc[i][j]);
            if (td == 0) {
                #pragma unroll
                for (int i = 0; i < 4; i++) dacc[i] += a[i];
            }
        }
        __syncthreads();
    }

    #pragma unroll
    for (int i = 0; i < 4; i++)
        #pragma unroll
        for (int j = 0; j < 4; j++)
            atomicAdd(&g_N[(size_t)bh * NFc * DHc + (tf + i) * DHc + td + j], acc[i][j]);
    if (td == 0) {
        #pragma unroll
        for (int i = 0; i < 4; i++)
            atomicAdd(&g_D[bh * NFc + tf + i], dacc[i]);
    }
}

// ---------------------------------------------------------------------------
// Combine: ctx[b,l,h*64+d] = (phi . N[:,d]) / (phi . D + S*EPS)
// grid: (Lseq/64, B*H), 256 threads (8 warps x 8 rows each).
// ---------------------------------------------------------------------------
__global__ void __launch_bounds__(256) combine_kernel() {
    int bh = blockIdx.y;
    int b = bh >> 4, h = bh & 15;
    int l0 = blockIdx.x * 64;

    __shared__ float Ns[NFc][DHc];
    __shared__ float Ds[NFc];
    __shared__ float sSE;

    int t = threadIdx.x;
    for (int e = t; e < NFc * DHc; e += 256)
        Ns[e / DHc][e % DHc] = g_N[(size_t)bh * NFc * DHc + e];
    if (t < NFc) Ds[t] = g_D[bh * NFc + t];
    __syncthreads();
    if (t == 0) {
        float s = 0.f;
        #pragma unroll
        for (int f = 0; f < NFc; f++) s += Ds[f];
        sSE = s * EPSf;
    }
    __syncthreads();

    int warp = t >> 5, lane = t & 31;
    #pragma unroll 1
    for (int r = 0; r < 8; r++) {
        int l = l0 + warp * 8 + r;
        const float* prow = &g_phi[((size_t)bh * Lseq + l) * NFc];
        float num0 = 0.f, num1 = 0.f, den = 0.f;
        #pragma unroll
        for (int f = 0; f < NFc; f++) {
            float p = prow[f];
            num0 = fmaf(p, Ns[f][lane], num0);
            num1 = fmaf(p, Ns[f][lane + 32], num1);
            den  = fmaf(p, Ds[f], den);
        }
        float invd = 1.0f / (den + sSE);
        size_t g = (size_t)(b * Lseq + l) * DIMc + h * DHc;
        g_ctx[g + lane]      = num0 * invd;
        g_ctx[g + lane + 32] = num1 * invd;
    }
}

// ---------------------------------------------------------------------------
// Launch
// ---------------------------------------------------------------------------
extern "C" void kernel_launch(void* const* d_in, const int* in_sizes, int n_in,
                              void* d_out, int out_size) {
    const float* x   = (const float*)d_in[0];
    const float* Wq  = (const float*)d_in[1];
    const float* bq  = (const float*)d_in[2];
    const float* Wk  = (const float*)d_in[3];
    const float* bk  = (const float*)d_in[4];
    const float* Wv  = (const float*)d_in[5];
    const float* bv  = (const float*)d_in[6];
    const float* Wo  = (const float*)d_in[7];
    const float* bo  = (const float*)d_in[8];
    const float* Wrf = (const float*)d_in[9];
    float* out = (float*)d_out;

    float *q, *k, *v, *ctx;
    cudaGetSymbolAddress((void**)&q,   g_q);
    cudaGetSymbolAddress((void**)&k,   g_k);
    cudaGetSymbolAddress((void**)&v,   g_v);
    cudaGetSymbolAddress((void**)&ctx, g_ctx);

    init_kernel<<<(BHc * NFc * DHc + 255) / 256, 256>>>();

    dim3 gg(DIMc / 128, Mrows / 128);
    sgemm_nt<<<gg, 256>>>(x, Wq, bq, q);
    sgemm_nt<<<gg, 256>>>(x, Wk, bk, k);
    sgemm_nt<<<gg, 256>>>(x, Wv, bv, v);

    logits_kernel<<<dim3(Lseq / 32, BHc), 256>>>(Wrf);
    nd_kernel<<<dim3(Lseq / 256, BHc), 256>>>();
    combine_kernel<<<dim3(Lseq / 64, BHc), 256>>>();

    sgemm_nt<<<gg, 256>>>(ctx, Wo, bo, out);
}